// round 15
// baseline (speedup 1.0000x reference)
#include <cuda_runtime.h>
#include <cstdint>

#define BB 512
#define LL 2048
#define CC 32
#define FULLM 0xffffffffu
#define LOG2E 1.4426950408889634f

__device__ double g_logz[BB];
__device__ double g_score[BB];
__device__ float  g_w[BB * CC], g_u[BB * CC];
__device__ float  g_P2[BB * CC * CC], g_P3[BB * CC * CC];  // S2^T, S3^T row-major
__device__ float  g_sw[BB], g_su[BB], g_s2[BB], g_s3[BB];  // log2 scales
__device__ int    g_bt[BB];
__device__ int    g_ticket;

__device__ __forceinline__ float rcp_approx(float x){float r;asm("rcp.approx.f32 %0,%1;":"=f"(r):"f"(x));return r;}
__device__ __forceinline__ float ex2_approx(float x){float r;asm("ex2.approx.f32 %0,%1;":"=f"(r):"f"(x));return r;}
__device__ __forceinline__ float lg2_approx(float x){float r;asm("lg2.approx.f32 %0,%1;":"=f"(r):"f"(x));return r;}
__device__ __forceinline__ uint32_t pack_bf16(float lo,float hi){
    uint32_t r;asm("cvt.rn.satfinite.bf16x2.f32 %0,%1,%2;":"=r"(r):"f"(hi),"f"(lo));return r;}
__device__ __forceinline__ unsigned long long mul2(unsigned long long a,unsigned long long b){
    unsigned long long r;asm("mul.rn.f32x2 %0,%1,%2;":"=l"(r):"l"(a),"l"(b));return r;}
__device__ __forceinline__ void fma2(unsigned long long&c,unsigned long long a,unsigned long long b){
    asm("fma.rn.f32x2 %0,%1,%2,%0;":"+l"(c):"l"(a),"l"(b));}
__device__ __forceinline__ unsigned long long add2(unsigned long long a,unsigned long long b){
    unsigned long long r;asm("add.rn.f32x2 %0,%1,%2;":"=l"(r):"l"(a),"l"(b));return r;}

__device__ __forceinline__ void mma_z(float d[4],const uint32_t a[4],uint32_t b0,uint32_t b1){
    asm("mma.sync.aligned.m16n8k16.row.col.f32.bf16.bf16.f32 "
        "{%0,%1,%2,%3},{%4,%5,%6,%7},{%8,%9},{%10,%10,%10,%10};"
        :"=f"(d[0]),"=f"(d[1]),"=f"(d[2]),"=f"(d[3])
        :"r"(a[0]),"r"(a[1]),"r"(a[2]),"r"(a[3]),"r"(b0),"r"(b1),"f"(0.f));}

// ---------------- fp32 vector core (R4, best measured) ----------------
#define CORE(PAR_,EE_) do{                                                    \
    __syncwarp();                                                             \
    const ulonglong2* pv_=(const ulonglong2*)(sv[(PAR_)]);                    \
    ulonglong2 q0_=pv_[0],q1_=pv_[1],q2_=pv_[2],q3_=pv_[3];                   \
    ulonglong2 q4_=pv_[4],q5_=pv_[5],q6_=pv_[6],q7_=pv_[7];                   \
    unsigned long long c0_=mul2(q0_.x,tp[0]),c1_=mul2(q0_.y,tp[1]);           \
    unsigned long long c2_=mul2(q1_.x,tp[2]),c3_=mul2(q1_.y,tp[3]);           \
    unsigned long long c4_=mul2(q2_.x,tp[4]),c5_=mul2(q2_.y,tp[5]);           \
    unsigned long long c6_=mul2(q3_.x,tp[6]),c7_=mul2(q3_.y,tp[7]);           \
    fma2(c0_,q4_.x,tp[8]);fma2(c1_,q4_.y,tp[9]);                              \
    fma2(c2_,q5_.x,tp[10]);fma2(c3_,q5_.y,tp[11]);                            \
    fma2(c4_,q6_.x,tp[12]);fma2(c5_,q6_.y,tp[13]);                            \
    fma2(c6_,q7_.x,tp[14]);fma2(c7_,q7_.y,tp[15]);                            \
    unsigned long long s__=add2(add2(add2(c0_,c1_),add2(c2_,c3_)),            \
                                add2(add2(c4_,c5_),add2(c6_,c7_)));           \
    float sl_,sh_;                                                            \
    asm("mov.b64 {%0,%1},%2;":"=f"(sl_),"=f"(sh_):"l"(s__));                  \
    vn=(sl_+sh_)*(EE_);                                                       \
    sv[(PAR_)^1][lane]=vn;                                                    \
}while(0)

#define PREP_EE(EVN_,RN_) do{                                                 \
    if(RN_){float v0b_=__shfl_sync(FULLM,vn,0);                               \
        ee=ex2_approx(EVN_)*rcp_approx(v0b_); Ml2+=lg2_approx(v0b_);          \
    } else ee=ex2_approx(EVN_);                                               \
}while(0)

// Vector segment: BLOCKS*8 + TAIL emission steps (+1 plain for BWD).
template<bool BWD, int BLOCKS, int TAIL>
__device__ float run_vec(const float* __restrict__ ep, const float* __restrict__ T,
                         int lane, float (*sv)[CC], float& vout)
{
    unsigned long long tp[16];
#pragma unroll
    for(int k=0;k<16;++k){
        float a,c;
        if(!BWD){a=__expf(T[lane*CC+2*k]);   c=__expf(T[lane*CC+2*k+1]);}
        else    {a=__expf(T[(2*k)*CC+lane]); c=__expf(T[(2*k+1)*CC+lane]);}
        asm("mov.b64 %0,{%1,%2};":"=l"(tp[k]):"f"(a),"f"(c));
    }
    const long D = BWD ? -(long)CC : (long)CC;
    float ebuf[8];
#pragma unroll
    for(int k=0;k<8;++k) ebuf[k]=ep[D*(1+k)]*LOG2E;
    float vn=__expf(ep[0]);
    sv[1][lane]=vn;
    float Ml2, ee;
    {   float v0=__shfl_sync(FULLM,vn,0);
        ee=ex2_approx(ebuf[0])*rcp_approx(v0); Ml2=lg2_approx(v0); }
    const float* pf=ep+D*9;
#pragma unroll 1
    for(int blk=0;blk<BLOCKS;++blk){
#pragma unroll
        for(int k=0;k<8;++k){
            ebuf[k]=pf[D*k]*LOG2E;
            CORE((1+k)&1, ee);
            PREP_EE(ebuf[(k+1)&7],(k&3)==3);
        }
        pf+=D*8;
    }
#pragma unroll
    for(int k=0;k<TAIL;++k){
        CORE((1+k)&1, ee);
        if(k<TAIL-1) PREP_EE(ebuf[k+1],(k&3)==3);
    }
    if(BWD){ ee=1.f; CORE((1+TAIL)&1, ee); }   // final plain T multiply
    vout=vn;
    return Ml2;
}

// ---------------- matrix segment: P <- (P*B)*D_t ----------------
__device__ __forceinline__ void prep_ef(float ef[8],float raw,int s0,int s1){
    float ex_=ex2_approx(raw*LOG2E);
#pragma unroll
    for(int j=0;j<4;++j){
        ef[2*j]  =__shfl_sync(FULLM,ex_,s0+8*j);
        ef[2*j+1]=__shfl_sync(FULLM,ex_,s1+8*j);
    }
}

// INDEPENDENT k-tile accumulators (e_/f_) + FADD merge: one HMMA latency/step.
#define MAT_STEP(NORM_) do{                                                   \
    uint32_t A_[2][2][4];                                                     \
    _Pragma("unroll") for(int mt=0;mt<2;++mt)                                 \
    _Pragma("unroll") for(int kt=0;kt<2;++kt){                                \
        A_[mt][kt][0]=pack_bf16(fv[mt][2*kt][0],  fv[mt][2*kt][1]);           \
        A_[mt][kt][1]=pack_bf16(fv[mt][2*kt][2],  fv[mt][2*kt][3]);           \
        A_[mt][kt][2]=pack_bf16(fv[mt][2*kt+1][0],fv[mt][2*kt+1][1]);         \
        A_[mt][kt][3]=pack_bf16(fv[mt][2*kt+1][2],fv[mt][2*kt+1][3]);         \
    }                                                                         \
    float e_[2][4][4], f_[2][4][4];                                           \
    _Pragma("unroll") for(int mt=0;mt<2;++mt)                                 \
    _Pragma("unroll") for(int nt=0;nt<4;++nt)                                 \
        mma_z(e_[mt][nt],A_[mt][0],Bf[0][nt][0],Bf[0][nt][1]);                \
    _Pragma("unroll") for(int mt=0;mt<2;++mt)                                 \
    _Pragma("unroll") for(int nt=0;nt<4;++nt)                                 \
        mma_z(f_[mt][nt],A_[mt][1],Bf[1][nt][0],Bf[1][nt][1]);                \
    _Pragma("unroll") for(int mt=0;mt<2;++mt)                                 \
    _Pragma("unroll") for(int nt=0;nt<4;++nt){                                \
        fv[mt][nt][0]=(e_[mt][nt][0]+f_[mt][nt][0])*ef[2*nt];                 \
        fv[mt][nt][1]=(e_[mt][nt][1]+f_[mt][nt][1])*ef[2*nt+1];               \
        fv[mt][nt][2]=(e_[mt][nt][2]+f_[mt][nt][2])*ef[2*nt];                 \
        fv[mt][nt][3]=(e_[mt][nt][3]+f_[mt][nt][3])*ef[2*nt+1];               \
    }                                                                         \
    if(NORM_){                                                                \
        float v0_=__shfl_sync(FULLM,fv[0][0][0],0);                           \
        float r_=rcp_approx(v0_); Ml2+=lg2_approx(v0_);                       \
        _Pragma("unroll") for(int mt=0;mt<2;++mt)                             \
        _Pragma("unroll") for(int nt=0;nt<4;++nt)                             \
        _Pragma("unroll") for(int q=0;q<4;++q) fv[mt][nt][q]*=r_;             \
    }                                                                         \
}while(0)

template<int BLOCKS>
__device__ float run_mat(int b,int T0,const float* __restrict__ em,
                         const float* __restrict__ T,
                         float* __restrict__ gP,int lane)
{
    const int tid=lane&3, gid=lane>>2, s0=2*tid, s1=s0+1;
    uint32_t Bf[2][4][2];
#pragma unroll
    for(int kt=0;kt<2;++kt)
#pragma unroll
    for(int nt=0;nt<4;++nt){
        int n=nt*8+gid, k0=kt*16+s0;
        Bf[kt][nt][0]=pack_bf16(__expf(T[n*CC+k0]),  __expf(T[n*CC+k0+1]));
        Bf[kt][nt][1]=pack_bf16(__expf(T[n*CC+k0+8]),__expf(T[n*CC+k0+9]));
    }
    float fv[2][4][4];
#pragma unroll
    for(int mt=0;mt<2;++mt)
#pragma unroll
    for(int nt=0;nt<4;++nt)
#pragma unroll
    for(int q=0;q<4;++q){
        int r=16*mt+gid+((q>>1)?8:0), c=8*nt+s0+(q&1);
        fv[mt][nt][q]=(r==c)?1.f:0.f;
    }
    float Ml2=0.f;
    const float* ep=em+lane;
    float ebuf[8];
#pragma unroll
    for(int k=0;k<8;++k) ebuf[k]=ep[(size_t)(T0+k)*CC];
    float ef[8];
    prep_ef(ef,ebuf[0],s0,s1);
    const float* pf=ep+(size_t)(T0+8)*CC;
#pragma unroll 1
    for(int blk=0;blk<BLOCKS;++blk){
#pragma unroll
        for(int k=0;k<8;++k){
            float rawn=ebuf[(k+1)&7];
            ebuf[k]=pf[k*CC];
            MAT_STEP((k&3)==3);
            prep_ef(ef,rawn,s0,s1);
        }
        pf+=8*CC;
    }
#pragma unroll
    for(int mt=0;mt<2;++mt)
#pragma unroll
    for(int nt=0;nt<4;++nt)
#pragma unroll
    for(int h=0;h<2;++h){
        int r=16*mt+gid+8*h, c=8*nt+s0;
        *(float2*)&gP[(size_t)b*1024 + r*32 + c]=
            make_float2(fv[mt][nt][2*h],fv[mt][nt][2*h+1]);
    }
    return Ml2;
}

__global__ void crf_init(){
    int i=threadIdx.x;
    if(i<BB) g_bt[i]=0;
    if(i==BB) g_ticket=0;
}

__device__ __forceinline__ void gticket_finish(int lane,float* out){
    int last=0;
    if(lane==0){__threadfence(); last=(atomicAdd(&g_ticket,1)==2*BB-1);}
    last=__shfl_sync(FULLM,last,0);
    if(last){
        __threadfence();
        double acc=0.0;
        for(int i=lane;i<BB;i+=32) acc+=__ldcg(&g_logz[i])-__ldcg(&g_score[i]);
#pragma unroll
        for(int o=16;o;o>>=1) acc+=__shfl_xor_sync(FULLM,acc,o);
        if(lane==0) out[0]=(float)(acc/(double)BB);
    }
}

__device__ void arrive_batch(int b,int lane,float* out){
    int go=0;
    if(lane==0){__threadfence(); go=(atomicAdd(&g_bt[b],1)==3);}
    go=__shfl_sync(FULLM,go,0);
    if(!go) return;
    __threadfence();
    double wv=(double)__ldcg(&g_w[b*CC+lane]);
    const float* p2=&g_P2[(size_t)b*1024];
    double y1=0.0;
#pragma unroll 4
    for(int j=0;j<32;++j) y1+=(double)__ldcg(&p2[j*32+lane])*__shfl_sync(FULLM,wv,j);
    const float* p3=&g_P3[(size_t)b*1024];
    double y2=0.0;
#pragma unroll 4
    for(int j=0;j<32;++j) y2+=(double)__ldcg(&p3[j*32+lane])*__shfl_sync(FULLM,y1,j);
    double s=(double)__ldcg(&g_u[b*CC+lane])*y2;
#pragma unroll
    for(int o=16;o;o>>=1) s+=__shfl_xor_sync(FULLM,s,o);
    if(lane==0){
        double m=(double)__ldcg(&g_sw[b])+(double)__ldcg(&g_su[b])
                +(double)__ldcg(&g_s2[b])+(double)__ldcg(&g_s3[b]);
        g_logz[b]=m*0.6931471805599453+log(s);
    }
    gticket_finish(lane,out);
}

// Segmentation: fwd t=1..576 | S2 t=577..1024 | S3 t=1025..1472 | bwd t=1473..2047
// blocks: [0,512) fwd | [512,1024) bwd | [1024,2048) matrix | [2048,2560) score
__global__ void __launch_bounds__(CC) crf_main(
    const float* __restrict__ emissions,
    const float* __restrict__ transitions,
    const int*   __restrict__ tags,
    const int*   __restrict__ mask,
    float*       __restrict__ out)
{
    __shared__ __align__(16) float sv[2][CC];
    const int lane=threadIdx.x, bid=blockIdx.x;

    if(bid<2*BB){
        const int b=bid&(BB-1);
        const bool isF=bid<BB;
        const float* em=emissions+(size_t)b*LL*CC;
        float vout, Ml2;
        if(isF) Ml2=run_vec<false,71,8>(em+lane,transitions,lane,sv,vout);          // 576 steps
        else    Ml2=run_vec<true ,71,6>(em+(size_t)(LL-1)*CC+lane,transitions,lane,sv,vout); // 574+1
        (isF?g_w:g_u)[b*CC+lane]=vout;
        if(lane==0) (isF?g_sw:g_su)[b]=Ml2;
        arrive_batch(b,lane,out);
    } else if(bid<4*BB){
        const int idx=bid-2*BB, seg=idx>>9, b=idx&(BB-1);
        const float* em=emissions+(size_t)b*LL*CC;
        float Ml2=run_mat<56>(b, seg?1025:577, em, transitions,
                              seg?g_P3:g_P2, lane);                           // 448 steps
        if(lane==0) (seg?g_s3:g_s2)[b]=Ml2;
        arrive_batch(b,lane,out);
    } else {
        const int b=bid-4*BB;
        const int* tg=tags+(size_t)b*LL;
        const int* mk=mask+(size_t)b*LL;
        const float* eb=emissions+(size_t)b*LL*CC;
        int ms=0;
        for(int t=lane;t<LL;t+=32) ms+=mk[t];
#pragma unroll
        for(int o=16;o;o>>=1) ms+=__shfl_xor_sync(FULLM,ms,o);
        double acc=0.0;
        for(int t=lane;t<LL-1;t+=32){
            int a=tg[t],c=tg[t+1];
            acc+=(double)(eb[t*CC+a]*(float)mk[t])
               +(double)(transitions[a*CC+c]*(float)mk[t+1]);
        }
#pragma unroll
        for(int o=16;o;o>>=1) acc+=__shfl_xor_sync(FULLM,acc,o);
        if(lane==0){
            int li=ms-1; if(li<0) li=0;
            int mc=ms;  if(mc<1) mc=1;
            acc+=(double)eb[(mc-1)*CC+tg[li]];
            g_score[b]=acc;
        }
        gticket_finish(lane,out);
    }
}

extern "C" void kernel_launch(void* const* d_in,const int* in_sizes,int n_in,
                              void* d_out,int out_size){
    const float* emissions  =(const float*)d_in[0];
    const float* transitions=(const float*)d_in[1];
    const int*   tags       =(const int*)d_in[2];
    const int*   mask       =(const int*)d_in[3];
    (void)in_sizes;(void)n_in;(void)out_size;
    crf_init<<<1,BB+32>>>();
    crf_main<<<5*BB,CC>>>(emissions,transitions,tags,mask,(float*)d_out);
}

// round 16
// speedup vs baseline: 1.0968x; 1.0968x over previous
#include <cuda_runtime.h>
#include <cstdint>

#define BB 512
#define LL 2048
#define CC 32
#define FULLM 0xffffffffu
#define LOG2E 1.4426950408889634f

__device__ double g_logz[BB];
__device__ double g_score[BB];
__device__ float  g_w[BB * CC], g_u[BB * CC];
__device__ float  g_P[BB * CC * CC];          // S^T row-major (matrix segment)
__device__ float  g_sw[BB], g_su[BB], g_sm[BB];
__device__ int    g_bt[BB];
__device__ int    g_ticket;

__device__ __forceinline__ float rcp_approx(float x){float r;asm("rcp.approx.f32 %0,%1;":"=f"(r):"f"(x));return r;}
__device__ __forceinline__ float ex2_approx(float x){float r;asm("ex2.approx.f32 %0,%1;":"=f"(r):"f"(x));return r;}
__device__ __forceinline__ float lg2_approx(float x){float r;asm("lg2.approx.f32 %0,%1;":"=f"(r):"f"(x));return r;}
__device__ __forceinline__ uint32_t pack_bf16(float lo,float hi){
    uint32_t r;asm("cvt.rn.satfinite.bf16x2.f32 %0,%1,%2;":"=r"(r):"f"(hi),"f"(lo));return r;}

// half-A MMA (rows 8-15 zero) with explicit C pair — vector core
__device__ __forceinline__ void mma8(float& d0,float& d1,
    uint32_t a0,uint32_t a2,uint32_t b0,uint32_t b1,float c0,float c1)
{
    float dz2,dz3;
    asm("mma.sync.aligned.m16n8k16.row.col.f32.bf16.bf16.f32 "
        "{%0,%1,%2,%3},{%4,%5,%6,%7},{%8,%9},{%10,%11,%12,%13};"
        :"=f"(d0),"=f"(d1),"=f"(dz2),"=f"(dz3)
        :"r"(a0),"r"(0u),"r"(a2),"r"(0u),"r"(b0),"r"(b1),
         "f"(c0),"f"(c1),"f"(0.f),"f"(0.f));
}
// full-A MMAs for the matrix segment (zero-C and accumulate forms)
__device__ __forceinline__ void mma_z(float d[4],const uint32_t a[4],uint32_t b0,uint32_t b1){
    asm("mma.sync.aligned.m16n8k16.row.col.f32.bf16.bf16.f32 "
        "{%0,%1,%2,%3},{%4,%5,%6,%7},{%8,%9},{%10,%10,%10,%10};"
        :"=f"(d[0]),"=f"(d[1]),"=f"(d[2]),"=f"(d[3])
        :"r"(a[0]),"r"(a[1]),"r"(a[2]),"r"(a[3]),"r"(b0),"r"(b1),"f"(0.f));}
__device__ __forceinline__ void mma_a(float d[4],const uint32_t a[4],uint32_t b0,uint32_t b1){
    asm("mma.sync.aligned.m16n8k16.row.col.f32.bf16.bf16.f32 "
        "{%0,%1,%2,%3},{%4,%5,%6,%7},{%8,%9},{%0,%1,%2,%3};"
        :"+f"(d[0]),"+f"(d[1]),"+f"(d[2]),"+f"(d[3])
        :"r"(a[0]),"r"(a[1]),"r"(a[2]),"r"(a[3]),"r"(b0),"r"(b1));}

// ---------------- vector MMA core (R10, best measured) ----------------
#define PREPE(RAW_) do {                                                      \
    float ex_ = ex2_approx((RAW_) * LOG2E);                                   \
    ef[0]=__shfl_sync(FULLM,ex_,s0);     ef[1]=__shfl_sync(FULLM,ex_,s1);     \
    ef[2]=__shfl_sync(FULLM,ex_,s0+8);   ef[3]=__shfl_sync(FULLM,ex_,s1+8);   \
    ef[4]=__shfl_sync(FULLM,ex_,s0+16);  ef[5]=__shfl_sync(FULLM,ex_,s1+16);  \
    ef[6]=__shfl_sync(FULLM,ex_,s0+24);  ef[7]=__shfl_sync(FULLM,ex_,s1+24);  \
} while (0)

#define MSTEP(NORM_) do {                                                     \
    float d0_,d1_,d2_,d3_,d4_,d5_,d6_,d7_;                                    \
    mma8(d0_,d1_, va[0],va[1], Bf[0][0][0],Bf[0][0][1], 0.f,0.f);             \
    mma8(d2_,d3_, va[0],va[1], Bf[0][1][0],Bf[0][1][1], 0.f,0.f);             \
    mma8(d4_,d5_, va[0],va[1], Bf[0][2][0],Bf[0][2][1], 0.f,0.f);             \
    mma8(d6_,d7_, va[0],va[1], Bf[0][3][0],Bf[0][3][1], 0.f,0.f);             \
    mma8(d0_,d1_, va[2],va[3], Bf[1][0][0],Bf[1][0][1], d0_,d1_);             \
    mma8(d2_,d3_, va[2],va[3], Bf[1][1][0],Bf[1][1][1], d2_,d3_);             \
    mma8(d4_,d5_, va[2],va[3], Bf[1][2][0],Bf[1][2][1], d4_,d5_);             \
    mma8(d6_,d7_, va[2],va[3], Bf[1][3][0],Bf[1][3][1], d6_,d7_);             \
    fv[0]=d0_*ef[0]; fv[1]=d1_*ef[1]; fv[2]=d2_*ef[2]; fv[3]=d3_*ef[3];       \
    fv[4]=d4_*ef[4]; fv[5]=d5_*ef[5]; fv[6]=d6_*ef[6]; fv[7]=d7_*ef[7];       \
    if (NORM_) {                                                              \
        float v0_=__shfl_sync(FULLM,fv[0],0);                                 \
        float r_=rcp_approx(v0_);                                             \
        Ml2+=lg2_approx(v0_);                                                 \
        fv[0]*=r_; fv[1]*=r_; fv[2]*=r_; fv[3]*=r_;                           \
        fv[4]*=r_; fv[5]*=r_; fv[6]*=r_; fv[7]*=r_;                           \
    }                                                                         \
    va[0]=pack_bf16(fv[0],fv[1]); va[1]=pack_bf16(fv[2],fv[3]);               \
    va[2]=pack_bf16(fv[4],fv[5]); va[3]=pack_bf16(fv[6],fv[7]);               \
} while (0)

// BLOCKS*8 + TAIL emission steps (+1 plain step when TRANS/backward).
template<int SGN, bool TRANS, int BLOCKS, int TAIL>
__device__ float run_vec(const float* __restrict__ ep,
                         const float* __restrict__ T,
                         float fv_out[8], int lane)
{
    const int tid=lane&3, gid=lane>>2, s0=2*tid, s1=s0+1;
    uint32_t Bf[2][4][2];
#pragma unroll
    for(int kt=0;kt<2;++kt)
#pragma unroll
    for(int nt=0;nt<4;++nt){
        int n=nt*8+gid, k0=kt*16+s0;
        float w00,w01,w10,w11;
        if(!TRANS){
            w00=__expf(T[n*CC+k0]);   w01=__expf(T[n*CC+k0+1]);
            w10=__expf(T[n*CC+k0+8]); w11=__expf(T[n*CC+k0+9]);
        }else{
            w00=__expf(T[(k0)*CC+n]);   w01=__expf(T[(k0+1)*CC+n]);
            w10=__expf(T[(k0+8)*CC+n]); w11=__expf(T[(k0+9)*CC+n]);
        }
        Bf[kt][nt][0]=pack_bf16(w00,w01);
        Bf[kt][nt][1]=pack_bf16(w10,w11);
    }

    float ebuf[8];
#pragma unroll
    for(int k=0;k<8;++k) ebuf[k]=ep[(long)SGN*CC*(1+k)];

    float ev0=ex2_approx(ep[0]*LOG2E);
    float fv[8];
    fv[0]=__shfl_sync(FULLM,ev0,s0);    fv[1]=__shfl_sync(FULLM,ev0,s1);
    fv[2]=__shfl_sync(FULLM,ev0,s0+8);  fv[3]=__shfl_sync(FULLM,ev0,s1+8);
    fv[4]=__shfl_sync(FULLM,ev0,s0+16); fv[5]=__shfl_sync(FULLM,ev0,s1+16);
    fv[6]=__shfl_sync(FULLM,ev0,s0+24); fv[7]=__shfl_sync(FULLM,ev0,s1+24);
    float v0i=__shfl_sync(FULLM,ev0,0);
    float rri=rcp_approx(v0i);
    float Ml2=lg2_approx(v0i);
    uint32_t va[4];
    va[0]=pack_bf16(fv[0]*rri,fv[1]*rri); va[1]=pack_bf16(fv[2]*rri,fv[3]*rri);
    va[2]=pack_bf16(fv[4]*rri,fv[5]*rri); va[3]=pack_bf16(fv[6]*rri,fv[7]*rri);

    float ef[8];
    PREPE(ebuf[0]);
    const float* pf=ep+(long)SGN*CC*9;

#pragma unroll 1
    for(int blk=0;blk<BLOCKS;++blk){
#pragma unroll
        for(int k=0;k<8;++k){
            float rawn=ebuf[(k+1)&7];
            ebuf[k]=pf[(long)SGN*CC*k];
            MSTEP((k&3)==3);
            PREPE(rawn);
        }
        pf+=(long)SGN*CC*8;
    }
#pragma unroll
    for(int k=0;k<TAIL;++k){
        float rawn=ebuf[k+1];
        MSTEP((k&3)==3);
        if(k<TAIL-1) PREPE(rawn);
    }
    if(TRANS){
#pragma unroll
        for(int j=0;j<8;++j) ef[j]=1.0f;
        MSTEP(false);
    }
#pragma unroll
    for(int j=0;j<8;++j) fv_out[j]=fv[j];
    return Ml2;
}

// ---------------- matrix segment (R14, chained — validated) ----------------
__device__ __forceinline__ void prep_ef8(float ef[8],float raw,int s0,int s1){
    float ex_=ex2_approx(raw*LOG2E);
#pragma unroll
    for(int j=0;j<4;++j){
        ef[2*j]  =__shfl_sync(FULLM,ex_,s0+8*j);
        ef[2*j+1]=__shfl_sync(FULLM,ex_,s1+8*j);
    }
}

#define MAT_STEP(NORM_) do{                                                   \
    uint32_t A_[2][2][4];                                                     \
    _Pragma("unroll") for(int mt=0;mt<2;++mt)                                 \
    _Pragma("unroll") for(int kt=0;kt<2;++kt){                                \
        A_[mt][kt][0]=pack_bf16(fm[mt][2*kt][0],  fm[mt][2*kt][1]);           \
        A_[mt][kt][1]=pack_bf16(fm[mt][2*kt][2],  fm[mt][2*kt][3]);           \
        A_[mt][kt][2]=pack_bf16(fm[mt][2*kt+1][0],fm[mt][2*kt+1][1]);         \
        A_[mt][kt][3]=pack_bf16(fm[mt][2*kt+1][2],fm[mt][2*kt+1][3]);         \
    }                                                                         \
    float d_[2][4][4];                                                        \
    _Pragma("unroll") for(int mt=0;mt<2;++mt)                                 \
    _Pragma("unroll") for(int nt=0;nt<4;++nt)                                 \
        mma_z(d_[mt][nt],A_[mt][0],Bf[0][nt][0],Bf[0][nt][1]);                \
    _Pragma("unroll") for(int mt=0;mt<2;++mt)                                 \
    _Pragma("unroll") for(int nt=0;nt<4;++nt)                                 \
        mma_a(d_[mt][nt],A_[mt][1],Bf[1][nt][0],Bf[1][nt][1]);                \
    _Pragma("unroll") for(int mt=0;mt<2;++mt)                                 \
    _Pragma("unroll") for(int nt=0;nt<4;++nt){                                \
        fm[mt][nt][0]=d_[mt][nt][0]*ef[2*nt];                                 \
        fm[mt][nt][1]=d_[mt][nt][1]*ef[2*nt+1];                               \
        fm[mt][nt][2]=d_[mt][nt][2]*ef[2*nt];                                 \
        fm[mt][nt][3]=d_[mt][nt][3]*ef[2*nt+1];                               \
    }                                                                         \
    if(NORM_){                                                                \
        float v0_=__shfl_sync(FULLM,fm[0][0][0],0);                           \
        float r_=rcp_approx(v0_); Ml2+=lg2_approx(v0_);                       \
        _Pragma("unroll") for(int mt=0;mt<2;++mt)                             \
        _Pragma("unroll") for(int nt=0;nt<4;++nt)                             \
        _Pragma("unroll") for(int q=0;q<4;++q) fm[mt][nt][q]*=r_;             \
    }                                                                         \
}while(0)

template<int BLOCKS>
__device__ float run_mat(int b,int T0,const float* __restrict__ em,
                         const float* __restrict__ T,
                         float* __restrict__ gP,int lane)
{
    const int tid=lane&3, gid=lane>>2, s0=2*tid, s1=s0+1;
    uint32_t Bf[2][4][2];
#pragma unroll
    for(int kt=0;kt<2;++kt)
#pragma unroll
    for(int nt=0;nt<4;++nt){
        int n=nt*8+gid, k0=kt*16+s0;
        Bf[kt][nt][0]=pack_bf16(__expf(T[n*CC+k0]),  __expf(T[n*CC+k0+1]));
        Bf[kt][nt][1]=pack_bf16(__expf(T[n*CC+k0+8]),__expf(T[n*CC+k0+9]));
    }
    float fm[2][4][4];
#pragma unroll
    for(int mt=0;mt<2;++mt)
#pragma unroll
    for(int nt=0;nt<4;++nt)
#pragma unroll
    for(int q=0;q<4;++q){
        int r=16*mt+gid+((q>>1)?8:0), c=8*nt+s0+(q&1);
        fm[mt][nt][q]=(r==c)?1.f:0.f;
    }
    float Ml2=0.f;
    const float* ep=em+lane;
    float ebuf[8];
#pragma unroll
    for(int k=0;k<8;++k) ebuf[k]=ep[(size_t)(T0+k)*CC];
    float ef[8];
    prep_ef8(ef,ebuf[0],s0,s1);
    const float* pf=ep+(size_t)(T0+8)*CC;
#pragma unroll 1
    for(int blk=0;blk<BLOCKS;++blk){
#pragma unroll
        for(int k=0;k<8;++k){
            float rawn=ebuf[(k+1)&7];
            ebuf[k]=pf[k*CC];
            MAT_STEP((k&3)==3);
            prep_ef8(ef,rawn,s0,s1);
        }
        pf+=8*CC;
    }
#pragma unroll
    for(int mt=0;mt<2;++mt)
#pragma unroll
    for(int nt=0;nt<4;++nt)
#pragma unroll
    for(int h=0;h<2;++h){
        int r=16*mt+gid+8*h, c=8*nt+s0;
        *(float2*)&gP[(size_t)b*1024 + r*32 + c]=
            make_float2(fm[mt][nt][2*h],fm[mt][nt][2*h+1]);
    }
    return Ml2;
}

__global__ void crf_init(){
    int i=threadIdx.x;
    if(i<BB) g_bt[i]=0;
    if(i==BB) g_ticket=0;
}

__device__ __forceinline__ void gticket_finish(int lane,float* out){
    int last=0;
    if(lane==0){__threadfence(); last=(atomicAdd(&g_ticket,1)==2*BB-1);}
    last=__shfl_sync(FULLM,last,0);
    if(last){
        __threadfence();
        double acc=0.0;
        for(int i=lane;i<BB;i+=32) acc+=__ldcg(&g_logz[i])-__ldcg(&g_score[i]);
#pragma unroll
        for(int o=16;o;o>>=1) acc+=__shfl_xor_sync(FULLM,acc,o);
        if(lane==0) out[0]=(float)(acc/(double)BB);
    }
}

// 3rd arrival per batch: logZ = ln2*(sw+su+sm) + ln(u . (P^T w))
__device__ void arrive_batch(int b,int lane,float* out){
    int go=0;
    if(lane==0){__threadfence(); go=(atomicAdd(&g_bt[b],1)==2);}
    go=__shfl_sync(FULLM,go,0);
    if(!go) return;
    __threadfence();
    double wv=(double)__ldcg(&g_w[b*CC+lane]);
    const float* p=&g_P[(size_t)b*1024];
    double y=0.0;
#pragma unroll 4
    for(int j=0;j<32;++j) y+=(double)__ldcg(&p[j*32+lane])*__shfl_sync(FULLM,wv,j);
    double s=(double)__ldcg(&g_u[b*CC+lane])*y;
#pragma unroll
    for(int o=16;o;o>>=1) s+=__shfl_xor_sync(FULLM,s,o);
    if(lane==0){
        double m=(double)__ldcg(&g_sw[b])+(double)__ldcg(&g_su[b])
                +(double)__ldcg(&g_sm[b]);
        g_logz[b]=m*0.6931471805599453+log(s);
    }
    gticket_finish(lane,out);
}

// fwd: e_0 + t=1..679 | mat: t=680..1359 | bwd: e_2047 + t=2046..1360 + plain
// blocks: [0,512) fwd | [512,1024) bwd | [1024,1536) mat | [1536,2048) score
__global__ void __launch_bounds__(CC) crf_main(
    const float* __restrict__ emissions,
    const float* __restrict__ transitions,
    const int*   __restrict__ tags,
    const int*   __restrict__ mask,
    float*       __restrict__ out)
{
    const int lane=threadIdx.x, bid=blockIdx.x;

    if(bid<2*BB){
        const int b=bid&(BB-1);
        const bool isF=bid<BB;
        const float* em=emissions+(size_t)b*LL*CC;
        float fv[8];
        float Ml2;
        if(isF) Ml2=run_vec<+1,false,84,7>(em+lane,transitions,fv,lane);            // 679 steps
        else    Ml2=run_vec<-1,true ,85,7>(em+(size_t)(LL-1)*CC+lane,transitions,fv,lane); // 687+1
        float* dst=isF?g_w:g_u;
        if(lane<4){
#pragma unroll
            for(int j=0;j<4;++j){
                dst[b*CC+8*j+2*lane]  =fv[2*j];
                dst[b*CC+8*j+2*lane+1]=fv[2*j+1];
            }
        }
        if(lane==0) (isF?g_sw:g_su)[b]=Ml2;
        arrive_batch(b,lane,out);
    } else if(bid<3*BB){
        const int b=bid-2*BB;
        const float* em=emissions+(size_t)b*LL*CC;
        float Ml2=run_mat<85>(b, 680, em, transitions, g_P, lane);            // 680 steps
        if(lane==0) g_sm[b]=Ml2;
        arrive_batch(b,lane,out);
    } else {
        const int b=bid-3*BB;
        const int* tg=tags+(size_t)b*LL;
        const int* mk=mask+(size_t)b*LL;
        const float* eb=emissions+(size_t)b*LL*CC;
        int ms=0;
        for(int t=lane;t<LL;t+=32) ms+=mk[t];
#pragma unroll
        for(int o=16;o;o>>=1) ms+=__shfl_xor_sync(FULLM,ms,o);
        double acc=0.0;
        for(int t=lane;t<LL-1;t+=32){
            int a=tg[t],c=tg[t+1];
            acc+=(double)(eb[t*CC+a]*(float)mk[t])
               +(double)(transitions[a*CC+c]*(float)mk[t+1]);
        }
#pragma unroll
        for(int o=16;o;o>>=1) acc+=__shfl_xor_sync(FULLM,acc,o);
        if(lane==0){
            int li=ms-1; if(li<0) li=0;
            int mc=ms;  if(mc<1) mc=1;
            acc+=(double)eb[(mc-1)*CC+tg[li]];
            g_score[b]=acc;
        }
        gticket_finish(lane,out);
    }
}

extern "C" void kernel_launch(void* const* d_in,const int* in_sizes,int n_in,
                              void* d_out,int out_size){
    const float* emissions  =(const float*)d_in[0];
    const float* transitions=(const float*)d_in[1];
    const int*   tags       =(const int*)d_in[2];
    const int*   mask       =(const int*)d_in[3];
    (void)in_sizes;(void)n_in;(void)out_size;
    crf_init<<<1,BB+32>>>();
    crf_main<<<4*BB,CC>>>(emissions,transitions,tags,mask,(float*)d_out);
}